// round 1
// baseline (speedup 1.0000x reference)
#include <cuda_runtime.h>
#include <math.h>

#define M_TOT   16384
#define DM      1024
#define DFF_    4096

// ---------------- scratch ----------------
// h,q,k,v,attn,x1: 6 x 16M floats; ff: 128M; gated: 64M; kv: 256K; kvp: 2M
#define OFF_H     0ull
#define OFF_Q     16777216ull
#define OFF_K     33554432ull
#define OFF_V     50331648ull
#define OFF_ATTN  67108864ull
#define OFF_X1    83886080ull
#define OFF_FF    100663296ull
#define OFF_GATED 234881024ull
#define OFF_KV    301989888ull
#define OFF_KVP   302252032ull
#define SCRATCH_TOT 304349184ull

__device__ __align__(16) float g_scratch[SCRATCH_TOT];

// ---------------- layernorm ----------------
__global__ __launch_bounds__(256) void ln_k(const float* __restrict__ x,
                                            const float* __restrict__ gamma,
                                            const float* __restrict__ beta,
                                            float* __restrict__ out)
{
    int row = blockIdx.x, tid = threadIdx.x;
    const float4* xr = (const float4*)(x + (size_t)row * DM);
    float4 v = xr[tid];
    float s  = v.x + v.y + v.z + v.w;
    float ss = v.x*v.x + v.y*v.y + v.z*v.z + v.w*v.w;
    #pragma unroll
    for (int o = 16; o; o >>= 1) {
        s  += __shfl_xor_sync(0xffffffffu, s,  o);
        ss += __shfl_xor_sync(0xffffffffu, ss, o);
    }
    __shared__ float shs[8], shss[8];
    __shared__ float smu, srs;
    int w = tid >> 5, lane = tid & 31;
    if (lane == 0) { shs[w] = s; shss[w] = ss; }
    __syncthreads();
    if (tid == 0) {
        float ts = 0.f, tss = 0.f;
        #pragma unroll
        for (int i = 0; i < 8; i++) { ts += shs[i]; tss += shss[i]; }
        float mu  = ts * (1.0f / DM);
        float var = tss * (1.0f / DM) - mu * mu;
        smu = mu;
        srs = rsqrtf(var + 1e-5f);
    }
    __syncthreads();
    float mu = smu, rs = srs;
    float4 g = ((const float4*)gamma)[tid];
    float4 b = ((const float4*)beta)[tid];
    float4 o;
    o.x = (v.x - mu) * rs * g.x + b.x;
    o.y = (v.y - mu) * rs * g.y + b.y;
    o.z = (v.z - mu) * rs * g.z + b.z;
    o.w = (v.w - mu) * rs * g.w + b.w;
    ((float4*)(out + (size_t)row * DM))[tid] = o;
}

// ---------------- tiled fp32 GEMM: C = A[MxK] @ B[KxN] + bias (+epilogue) --------
// EPI: 0 = bias only, 1 = bias + (elu(x)+1), 2 = bias + residual R
template<int EPI>
__global__ __launch_bounds__(256) void gemm_k(const float* __restrict__ A,
                                              const float* __restrict__ B,
                                              const float* __restrict__ bias,
                                              const float* __restrict__ R,
                                              float* __restrict__ C,
                                              int M, int N, int K)
{
    __shared__ float As[8][128];   // transposed A tile
    __shared__ float Bs[8][128];
    int tid = threadIdx.x;
    int tx = tid & 15, ty = tid >> 4;
    const float* Ab = A + (size_t)blockIdx.y * 128 * K;
    const float* Bb = B + blockIdx.x * 128;
    int arow = tid >> 1, acol = (tid & 1) * 4;
    int brow = tid >> 5, bcol = (tid & 31) * 4;
    float acc[8][8];
    #pragma unroll
    for (int i = 0; i < 8; i++)
        #pragma unroll
        for (int j = 0; j < 8; j++) acc[i][j] = 0.f;

    for (int k0 = 0; k0 < K; k0 += 8) {
        float4 a4 = *(const float4*)(Ab + (size_t)arow * K + k0 + acol);
        As[acol + 0][arow] = a4.x;
        As[acol + 1][arow] = a4.y;
        As[acol + 2][arow] = a4.z;
        As[acol + 3][arow] = a4.w;
        *(float4*)&Bs[brow][bcol] = *(const float4*)(Bb + (size_t)(k0 + brow) * N + bcol);
        __syncthreads();
        #pragma unroll
        for (int kk = 0; kk < 8; kk++) {
            float4 a0 = *(const float4*)&As[kk][ty * 8];
            float4 a1 = *(const float4*)&As[kk][ty * 8 + 4];
            float4 b0 = *(const float4*)&Bs[kk][tx * 8];
            float4 b1 = *(const float4*)&Bs[kk][tx * 8 + 4];
            float af[8] = {a0.x,a0.y,a0.z,a0.w,a1.x,a1.y,a1.z,a1.w};
            float bf[8] = {b0.x,b0.y,b0.z,b0.w,b1.x,b1.y,b1.z,b1.w};
            #pragma unroll
            for (int i = 0; i < 8; i++)
                #pragma unroll
                for (int j = 0; j < 8; j++)
                    acc[i][j] += af[i] * bf[j];
        }
        __syncthreads();
    }

    int row0 = blockIdx.y * 128 + ty * 8;
    int col0 = blockIdx.x * 128 + tx * 8;
    #pragma unroll
    for (int i = 0; i < 8; i++) {
        size_t base = (size_t)(row0 + i) * N + col0;
        #pragma unroll
        for (int j = 0; j < 8; j += 4) {
            float4 bb = *(const float4*)(bias + col0 + j);
            float vals[4];
            vals[0] = acc[i][j + 0] + bb.x;
            vals[1] = acc[i][j + 1] + bb.y;
            vals[2] = acc[i][j + 2] + bb.z;
            vals[3] = acc[i][j + 3] + bb.w;
            if (EPI == 1) {
                #pragma unroll
                for (int t = 0; t < 4; t++)
                    vals[t] = (vals[t] > 0.f) ? (vals[t] + 1.f) : expf(vals[t]);
            }
            if (EPI == 2) {
                float4 rr = *(const float4*)(R + base + j);
                vals[0] += rr.x; vals[1] += rr.y; vals[2] += rr.z; vals[3] += rr.w;
            }
            *(float4*)(C + base + j) = make_float4(vals[0], vals[1], vals[2], vals[3]);
        }
    }
}

// ---------------- kv = sum_s k[s,d] v[s,e] per (b,h), split over S --------------
__global__ __launch_bounds__(256) void kv_partial_k(const float* __restrict__ Kp,
                                                    const float* __restrict__ Vp,
                                                    float* __restrict__ kvp)
{
    int bh = blockIdx.x, sp = blockIdx.y;     // bh: 0..63, sp: 0..7
    int b = bh >> 4, h = bh & 15;
    int tid = threadIdx.x;
    __shared__ float ks[32][64];
    __shared__ float vs[32][64];
    float acc[4][4];
    #pragma unroll
    for (int i = 0; i < 4; i++)
        #pragma unroll
        for (int j = 0; j < 4; j++) acc[i][j] = 0.f;

    int d0 = (tid >> 4) * 4, e0 = (tid & 15) * 4;
    size_t base = ((size_t)b * 4096) * DM + h * 64;
    for (int s0 = sp * 512; s0 < sp * 512 + 512; s0 += 32) {
        #pragma unroll
        for (int i = 0; i < 2; i++) {
            int f = tid + i * 256;
            int r = f >> 4, c = (f & 15) * 4;
            size_t off = base + (size_t)(s0 + r) * DM + c;
            *(float4*)&ks[r][c] = *(const float4*)(Kp + off);
            *(float4*)&vs[r][c] = *(const float4*)(Vp + off);
        }
        __syncthreads();
        #pragma unroll
        for (int ssm = 0; ssm < 32; ssm++) {
            float4 kd4 = *(const float4*)&ks[ssm][d0];
            float4 ve4 = *(const float4*)&vs[ssm][e0];
            float kd[4] = {kd4.x, kd4.y, kd4.z, kd4.w};
            float ve[4] = {ve4.x, ve4.y, ve4.z, ve4.w};
            #pragma unroll
            for (int i = 0; i < 4; i++)
                #pragma unroll
                for (int j = 0; j < 4; j++)
                    acc[i][j] += kd[i] * ve[j];
        }
        __syncthreads();
    }
    float* outp = kvp + ((size_t)sp * 64 + bh) * 4096;
    #pragma unroll
    for (int i = 0; i < 4; i++)
        *(float4*)(outp + (d0 + i) * 64 + e0) =
            make_float4(acc[i][0], acc[i][1], acc[i][2], acc[i][3]);
}

__global__ __launch_bounds__(256) void kv_reduce_k(const float* __restrict__ kvp,
                                                   float* __restrict__ kv)
{
    int i = blockIdx.x * 256 + threadIdx.x;   // < 64*4096
    float s = 0.f;
    #pragma unroll
    for (int sp = 0; sp < 8; sp++) s += kvp[(size_t)sp * 262144 + i];
    kv[i] = s;
}

// ---------------- attn[s,e] = sum_d q[s,d] kv[d,e] per (b,h) --------------------
__global__ __launch_bounds__(256) void attn_k(const float* __restrict__ Q,
                                              const float* __restrict__ KV,
                                              float* __restrict__ O)
{
    int bh = blockIdx.x, st = blockIdx.y;
    int b = bh >> 4, h = bh & 15;
    int tid = threadIdx.x;
    __shared__ float kvs[64][64];
    __shared__ float qs[64][68];   // padded vs bank conflicts
    const float* kvsrc = KV + (size_t)bh * 4096;
    #pragma unroll
    for (int i = 0; i < 4; i++) {
        int f = tid + i * 256;
        int r = f >> 4, c = (f & 15) * 4;
        *(float4*)&kvs[r][c] = *(const float4*)(kvsrc + r * 64 + c);
    }
    size_t qbase = ((size_t)b * 4096 + st * 64) * DM + h * 64;
    #pragma unroll
    for (int i = 0; i < 4; i++) {
        int f = tid + i * 256;
        int r = f >> 4, c = (f & 15) * 4;
        *(float4*)&qs[r][c] = *(const float4*)(Q + qbase + (size_t)r * DM + c);
    }
    __syncthreads();
    int r = tid >> 2, e0 = (tid & 3) * 16;
    float acc[16];
    #pragma unroll
    for (int j = 0; j < 16; j++) acc[j] = 0.f;
    #pragma unroll 8
    for (int d = 0; d < 64; d++) {
        float qd = qs[r][d];
        #pragma unroll
        for (int j = 0; j < 16; j++) acc[j] += qd * kvs[d][e0 + j];
    }
    float* orow = O + qbase + (size_t)r * DM + e0;
    #pragma unroll
    for (int j = 0; j < 16; j += 4)
        *(float4*)(orow + j) = make_float4(acc[j], acc[j+1], acc[j+2], acc[j+3]);
}

// ---------------- geglu: out = gelu_exact(ff[:,:4096]) * ff[:,4096:] ------------
__global__ __launch_bounds__(256) void geglu_k(const float* __restrict__ ff,
                                               float* __restrict__ out)
{
    size_t m = blockIdx.x;
    int tid = threadIdx.x;
    const float4* gp = (const float4*)(ff + m * 8192);
    const float4* lp = (const float4*)(ff + m * 8192 + 4096);
    float4* op = (float4*)(out + m * 4096);
    const float inv_sqrt2 = 0.70710678118654752f;
    #pragma unroll
    for (int i = 0; i < 4; i++) {
        int idx = tid + i * 256;
        float4 g = gp[idx], l = lp[idx];
        float4 o;
        o.x = 0.5f * g.x * (1.f + erff(g.x * inv_sqrt2)) * l.x;
        o.y = 0.5f * g.y * (1.f + erff(g.y * inv_sqrt2)) * l.y;
        o.z = 0.5f * g.z * (1.f + erff(g.z * inv_sqrt2)) * l.z;
        o.w = 0.5f * g.w * (1.f + erff(g.w * inv_sqrt2)) * l.w;
        op[idx] = o;
    }
}

// ---------------- launch ----------------
extern "C" void kernel_launch(void* const* d_in, const int* in_sizes, int n_in,
                              void* d_out, int out_size)
{
    const float* x   = (const float*)d_in[0];
    const float* wq  = (const float*)d_in[1];
    const float* bq  = (const float*)d_in[2];
    const float* wk  = (const float*)d_in[3];
    const float* bk  = (const float*)d_in[4];
    const float* wv  = (const float*)d_in[5];
    const float* bv  = (const float*)d_in[6];
    const float* wo  = (const float*)d_in[7];
    const float* bo  = (const float*)d_in[8];
    const float* w1  = (const float*)d_in[9];
    const float* b1  = (const float*)d_in[10];
    const float* w2  = (const float*)d_in[11];
    const float* b2  = (const float*)d_in[12];
    const float* g1  = (const float*)d_in[13];
    const float* be1 = (const float*)d_in[14];
    const float* g2  = (const float*)d_in[15];
    const float* be2 = (const float*)d_in[16];
    float* out = (float*)d_out;

    void* sp = nullptr;
    cudaGetSymbolAddress(&sp, g_scratch);
    float* S     = (float*)sp;
    float* h     = S + OFF_H;
    float* q     = S + OFF_Q;
    float* k     = S + OFF_K;
    float* v     = S + OFF_V;
    float* attn  = S + OFF_ATTN;
    float* x1    = S + OFF_X1;
    float* ffb   = S + OFF_FF;
    float* gated = S + OFF_GATED;
    float* kv    = S + OFF_KV;
    float* kvp   = S + OFF_KVP;

    dim3 g1024(DM / 128, M_TOT / 128);      // (8, 128)
    dim3 g8192((2 * DFF_) / 128, M_TOT / 128); // (64, 128)

    // 1. LN1
    ln_k<<<M_TOT, 256>>>(x, g1, be1, h);
    // 2-4. q/k/v projections (q,k with fused elu+1)
    gemm_k<1><<<g1024, 256>>>(h, wq, bq, nullptr, q, M_TOT, DM, DM);
    gemm_k<1><<<g1024, 256>>>(h, wk, bk, nullptr, k, M_TOT, DM, DM);
    gemm_k<0><<<g1024, 256>>>(h, wv, bv, nullptr, v, M_TOT, DM, DM);
    // 5. kv = K^T V per (b,h), deterministic split-S
    kv_partial_k<<<dim3(64, 8), 256>>>(k, v, kvp);
    kv_reduce_k<<<1024, 256>>>(kvp, kv);
    // 6. attn = q @ kv
    attn_k<<<dim3(64, 64), 256>>>(q, kv, attn);
    // 7. out proj + residual with original x
    gemm_k<2><<<g1024, 256>>>(attn, wo, bo, x, x1, M_TOT, DM, DM);
    // 8. LN2
    ln_k<<<M_TOT, 256>>>(x1, g2, be2, h);
    // 9. FF1 (N=8192)
    gemm_k<0><<<g8192, 256>>>(h, w1, b1, nullptr, ffb, M_TOT, 2 * DFF_, DM);
    // 10. GEGLU
    geglu_k<<<M_TOT, 256>>>(ffb, gated);
    // 11. FF2 + residual -> d_out
    gemm_k<2><<<g1024, 256>>>(gated, w2, b2, x1, out, M_TOT, DM, DFF_);
}